// round 9
// baseline (speedup 1.0000x reference)
#include <cuda_runtime.h>
#include <cuda_bf16.h>
#include <cstdint>

#define DD 64
#define KC 512
#define ROWSB 128
#define NTHR 256
#define NCTA 296            // 2 CTAs per SM
#define MARG_P 5600000u     // 5e-3 key margin * 2^21 * 512 (+slack), R6-proven margin
#define SCALE 2097152.0f    // 2^21
#define NEG2SCALE -4194304.0f

#if defined(__CUDA_ARCH__) && (defined(__CUDA_ARCH_FEAT_SM103_ALL) || defined(__CUDA_ARCH_FEAT_SM100_ALL) || defined(__CUDA_ARCH_FEAT_SM101_ALL))
#define HAS_TCGEN05 1
#else
#define HAS_TCGEN05 0
#endif

// ---- smem byte offsets ----
#define MB_DFULL(b)  ((b) * 8)          // 0,8    count 1 (commit)
#define MB_DFREE(b)  (16 + (b) * 8)     // 16,24  count 8 (lane0 per warp)
#define MB_ARDY(b)   (32 + (b) * 8)     // 32,40  count 128 (builders)
#define TMEM_SLOT    48
#define CS_OFF       128                // 512 f32 exact csq
#define PRE_OFF      2176               // 512 f32 (csq+2)*2^21
#define QT_OFF       4224               // 256 threads x 4 u32
#define SIDX_OFF     8320               // 128 int
#define A_OFF(b)     (10240 + (b) * 16384)   // 2 x 16KB bf16 h-limb, SW128
#define B_OFF        43008              // 64KB bf16 h-limb, SW128 (1024-aligned)
#define SMEM_TOTAL   108544

__device__ __forceinline__ uint32_t smem_u32(const void* p) {
    uint32_t a;
    asm("{ .reg .u64 t; cvta.to.shared.u64 t, %1; cvt.u32.u64 %0, t; }" : "=r"(a) : "l"(p));
    return a;
}
__device__ __forceinline__ uint32_t sw128(uint32_t off) { return off ^ ((off >> 3) & 0x70); }

#if HAS_TCGEN05
__device__ __forceinline__ uint32_t elect1() {
    uint32_t p;
    asm volatile("{ .reg .pred p; elect.sync _|p, 0xFFFFFFFF; selp.b32 %0, 1, 0, p; }" : "=r"(p));
    return p;
}
__device__ __forceinline__ void mbar_init(uint32_t a, uint32_t cnt) {
    asm volatile("mbarrier.init.shared.b64 [%0], %1;" :: "r"(a), "r"(cnt) : "memory");
}
__device__ __forceinline__ void mbar_arrive(uint32_t a) {
    asm volatile("mbarrier.arrive.release.cta.shared::cta.b64 _, [%0];" :: "r"(a) : "memory");
}
__device__ __forceinline__ void mbar_wait(uint32_t a, uint32_t parity) {
    asm volatile(
        "{\n\t.reg .pred P;\n"
        "WL_%=:\n\t"
        "mbarrier.try_wait.parity.acquire.cta.shared::cta.b64 P, [%0], %1, 0x989680;\n\t"
        "@!P bra WL_%=;\n\t}"
        :: "r"(a), "r"(parity) : "memory");
}
__device__ __forceinline__ void fence_async() {
    asm volatile("fence.proxy.async.shared::cta;" ::: "memory");
}
__device__ __forceinline__ void tmem_alloc(uint32_t slot, uint32_t ncols) {
    asm volatile("tcgen05.alloc.cta_group::1.sync.aligned.shared::cta.b32 [%0], %1;"
                 :: "r"(slot), "r"(ncols) : "memory");
}
__device__ __forceinline__ void tmem_relinquish() {
    asm volatile("tcgen05.relinquish_alloc_permit.cta_group::1.sync.aligned;");
}
__device__ __forceinline__ void tmem_dealloc(uint32_t base, uint32_t ncols) {
    asm volatile("tcgen05.dealloc.cta_group::1.sync.aligned.b32 %0, %1;" :: "r"(base), "r"(ncols));
}
__device__ __forceinline__ void mma_f16_ss(uint32_t d, uint64_t ad, uint64_t bd,
                                           uint32_t idesc, uint32_t en) {
    asm volatile(
        "{\n\t.reg .pred p;\n\t"
        "setp.ne.u32 p, %5, 0;\n\t"
        "tcgen05.mma.cta_group::1.kind::f16 [%0], %1, %2, %3, {%4, %4, %4, %4}, p;\n\t}"
        :: "r"(d), "l"(ad), "l"(bd), "r"(idesc), "r"(0u), "r"(en) : "memory");
}
__device__ __forceinline__ void mma_commit(uint32_t mbar) {
    asm volatile("tcgen05.commit.cta_group::1.mbarrier::arrive::one.shared::cluster.b64 [%0];"
                 :: "r"(mbar) : "memory");
}
__device__ __forceinline__ void fence_tc_after() {
    asm volatile("tcgen05.fence::after_thread_sync;" ::: "memory");
}
__device__ __forceinline__ void fence_tc_before() {
    asm volatile("tcgen05.fence::before_thread_sync;" ::: "memory");
}
#define LDTM_X32(r, a) \
    asm volatile("tcgen05.ld.sync.aligned.32x32b.x32.b32 " \
        "{%0,%1,%2,%3,%4,%5,%6,%7,%8,%9,%10,%11,%12,%13,%14,%15," \
        "%16,%17,%18,%19,%20,%21,%22,%23,%24,%25,%26,%27,%28,%29,%30,%31}, [%32];" \
        : "=r"((r)[0]),"=r"((r)[1]),"=r"((r)[2]),"=r"((r)[3]),"=r"((r)[4]),"=r"((r)[5]), \
          "=r"((r)[6]),"=r"((r)[7]),"=r"((r)[8]),"=r"((r)[9]),"=r"((r)[10]),"=r"((r)[11]), \
          "=r"((r)[12]),"=r"((r)[13]),"=r"((r)[14]),"=r"((r)[15]),"=r"((r)[16]),"=r"((r)[17]), \
          "=r"((r)[18]),"=r"((r)[19]),"=r"((r)[20]),"=r"((r)[21]),"=r"((r)[22]),"=r"((r)[23]), \
          "=r"((r)[24]),"=r"((r)[25]),"=r"((r)[26]),"=r"((r)[27]),"=r"((r)[28]),"=r"((r)[29]), \
          "=r"((r)[30]),"=r"((r)[31]) : "r"(a))
__device__ __forceinline__ void tmem_wait_ld() {
    asm volatile("tcgen05.wait::ld.sync.aligned;" ::: "memory");
}
#endif

#define DESC_BASE 0x4000404000010000ULL
__device__ __forceinline__ uint64_t mk_desc(uint32_t addr) {
    return DESC_BASE | ((uint64_t)(addr >> 4) & 0x3FFF);
}
#define IDESC 0x8200490u   // f32 acc, bf16 a/b, M=128, N=128 (proven R3-R8)

__device__ __forceinline__ uint32_t packbf(float a, float b) {
    return (uint32_t)__bfloat16_as_ushort(__float2bfloat16(a)) |
           ((uint32_t)__bfloat16_as_ushort(__float2bfloat16(b)) << 16);
}
__device__ __forceinline__ uint32_t umn(uint32_t a, uint32_t b) { return a < b ? a : b; }
__device__ __forceinline__ uint32_t umx(uint32_t a, uint32_t b) { return a > b ? a : b; }

__global__ void __launch_bounds__(NTHR, 2)
vq_persist(const float* __restrict__ x, const float* __restrict__ cbk,
           float* __restrict__ out, int n) {
    extern __shared__ char smem[];
    const int tid = threadIdx.x;
    const int bid = blockIdx.x;
    const size_t nD = (size_t)n * DD;
    float* Cs = (float*)(smem + CS_OFF);

#if HAS_TCGEN05
    const uint32_t sb = smem_u32(smem);
    const int wid = tid >> 5;
    const int lane = tid & 31;
    float* pre = (float*)(smem + PRE_OFF);
    uint32_t* QT = (uint32_t*)(smem + QT_OFF);
    int* sidx = (int*)(smem + SIDX_OFF);

    const int ntiles = (n + ROWSB - 1) / ROWSB;
    const int nt = (ntiles > bid) ? (ntiles - bid + NCTA - 1) / NCTA : 0;
    const int gtot = nt * 4;

    // ---------- startup ----------
    if (tid == 0) {
        for (int b = 0; b < 2; ++b) {
            mbar_init(sb + MB_DFULL(b), 1);
            mbar_init(sb + MB_DFREE(b), 8);
            mbar_init(sb + MB_ARDY(b), 128);
        }
    }
    __syncthreads();
    if (wid == 0) { tmem_alloc(sb + TMEM_SLOT, 256); tmem_relinquish(); }

    // B h-limb: 512x64 -> bf16 SW128 (128B per code row)
    for (int i = tid; i < KC * DD / 4; i += NTHR) {
        int code = i >> 4, kq = i & 15;
        float4 v = __ldg(((const float4*)cbk) + i);
        uint64_t u = (uint64_t)packbf(v.x, v.y) | ((uint64_t)packbf(v.z, v.w) << 32);
        *(uint64_t*)(smem + B_OFF + sw128(code * 128 + kq * 8)) = u;
    }
    // exact csq (reference rounding) + filter prescale
    for (int c = tid; c < KC; c += NTHR) {
        float s = 0.0f;
        const float* cr = cbk + c * DD;
        for (int k = 0; k < DD; ++k) {
            float v = __ldg(cr + k);
            s = __fadd_rn(s, __fmul_rn(v, v));
        }
        Cs[c] = s;
        pre[c] = (s + 2.0f) * SCALE;
    }
    // build A[0] for tile 0
    if (tid < 128 && nt > 0) {
        const int grow = bid * ROWSB + tid;
        float4 f[16];
        if (grow < n) {
            const float4* xr = (const float4*)(x + (size_t)grow * DD);
            #pragma unroll
            for (int k4 = 0; k4 < 16; ++k4) f[k4] = __ldg(xr + k4);
        } else {
            #pragma unroll
            for (int k4 = 0; k4 < 16; ++k4) f[k4] = make_float4(0.f, 0.f, 0.f, 0.f);
        }
        #pragma unroll
        for (int c8 = 0; c8 < 8; ++c8) {
            float4 a = f[c8 * 2], b = f[c8 * 2 + 1];
            uint4 u;
            u.x = packbf(a.x, a.y); u.y = packbf(a.z, a.w);
            u.z = packbf(b.x, b.y); u.w = packbf(b.z, b.w);
            *(uint4*)(smem + A_OFF(0) + sw128(tid * 128 + c8 * 16)) = u;
        }
    }
    fence_async();
    __syncthreads();
    const uint32_t tmem = *(volatile uint32_t*)(smem + TMEM_SLOT);

    const int sub = wid & 3;
    const int qh = wid >> 2;              // code half within a 128-code chunk
    const int srow = sub * 32 + lane;
    const uint64_t bdesc = mk_desc(sb + B_OFF);
    const int iss = (wid == 0) && elect1();

    // prologue: issue chunks g=0,1 (tile 0, A buf 0)
    if (iss && nt > 0) {
        const uint64_t adesc = mk_desc(sb + A_OFF(0));
        #pragma unroll
        for (int g = 0; g < 2; ++g) {
            const uint64_t bq = bdesc + (uint32_t)((g & 3) * 1024);
            const uint32_t dcol = tmem + (g & 1) * 128;
            #pragma unroll
            for (int k = 0; k < 4; ++k)
                mma_f16_ss(dcol, adesc + k * 2, bq + k * 2, IDESC, k != 0);
            mma_commit(sb + MB_DFULL(g & 1));
        }
    }

    // ---------- main loop ----------
    for (int it = 0; it < nt; ++it) {
        const int tile = bid + it * NCTA;

        // build A for tile it+1 (overlaps everything)
        if (it + 1 < nt) {
            if (tid < 128) {
                const int ab = (it + 1) & 1;
                const int grow2 = (bid + (it + 1) * NCTA) * ROWSB + tid;
                float4 f[16];
                if (grow2 < n) {
                    const float4* xr = (const float4*)(x + (size_t)grow2 * DD);
                    #pragma unroll
                    for (int k4 = 0; k4 < 16; ++k4) f[k4] = __ldg(xr + k4);
                } else {
                    #pragma unroll
                    for (int k4 = 0; k4 < 16; ++k4) f[k4] = make_float4(0.f, 0.f, 0.f, 0.f);
                }
                #pragma unroll
                for (int c8 = 0; c8 < 8; ++c8) {
                    float4 a = f[c8 * 2], b = f[c8 * 2 + 1];
                    uint4 u;
                    u.x = packbf(a.x, a.y); u.y = packbf(a.z, a.w);
                    u.z = packbf(b.x, b.y); u.w = packbf(b.z, b.w);
                    *(uint4*)(smem + A_OFF(ab) + sw128(tid * 128 + c8 * 16)) = u;
                }
                fence_async();
                mbar_arrive(sb + MB_ARDY(ab));
            }
        }

        // register top-4 (packed key|code), ascending
        uint32_t m1 = 0xFFFFFFFFu, m2 = 0xFFFFFFFFu, m3 = 0xFFFFFFFFu, m4 = 0xFFFFFFFFu;

        for (int c = 0; c < 4; ++c) {
            const int g = it * 4 + c;
            const int buf = g & 1;
            const uint32_t ph = (uint32_t)((g >> 1) & 1);

            mbar_wait(sb + MB_DFULL(buf), ph);
            fence_tc_after();
            uint32_t rg0[32], rg1[32];
            LDTM_X32(rg0, tmem + buf * 128 + qh * 64);
            LDTM_X32(rg1, tmem + buf * 128 + qh * 64 + 32);
            tmem_wait_ld();
            fence_tc_before();
            if (lane == 0) mbar_arrive(sb + MB_DFREE(buf));

            // issuer: launch chunk g+2 (2 ahead)
            if (iss) {
                const int g2 = g + 2;
                if (g2 < gtot) {
                    if (c == 2) {
                        const int t2 = it + 1;
                        mbar_wait(sb + MB_ARDY(t2 & 1), (uint32_t)(((t2 - 1) >> 1) & 1));
                    }
                    mbar_wait(sb + MB_DFREE(buf), ph);
                    const int tile2 = g2 >> 2;
                    const uint64_t adesc = mk_desc(sb + A_OFF(tile2 & 1));
                    const uint64_t bq = bdesc + (uint32_t)((g2 & 3) * 1024);
                    const uint32_t dcol = tmem + (g2 & 1) * 128;
                    #pragma unroll
                    for (int k = 0; k < 4; ++k)
                        mma_f16_ss(dcol, adesc + k * 2, bq + k * 2, IDESC, k != 0);
                    mma_commit(sb + MB_DFULL(g2 & 1));
                }
            }

            // branch-free filter: 64 codes, 2 reg batches
            const int cb = c * 128 + qh * 64;
            #pragma unroll
            for (int h = 0; h < 2; ++h) {
                const uint32_t* rg = h ? rg1 : rg0;
                const int base = cb + h * 32;
                #pragma unroll
                for (int j4 = 0; j4 < 8; ++j4) {
                    float4 p4 = *(const float4*)(pre + base + j4 * 4);
                    #pragma unroll
                    for (int jj = 0; jj < 4; ++jj) {
                        float pv = (jj == 0) ? p4.x : (jj == 1) ? p4.y : (jj == 2) ? p4.z : p4.w;
                        float k = __fmaf_rn(__uint_as_float(rg[j4 * 4 + jj]), NEG2SCALE, pv);
                        uint32_t pk = (__float2uint_rz(k) << 9) + (uint32_t)(base + j4 * 4 + jj);
                        uint32_t t1 = umx(m1, pk); m1 = umn(m1, pk);
                        uint32_t t2 = umx(m2, t1); m2 = umn(m2, t1);
                        uint32_t t3 = umx(m3, t2); m3 = umn(m3, t2);
                        m4 = umn(m4, t3);
                    }
                }
            }
        }

        // publish per-thread top-4
        {
            uint4 u; u.x = m1; u.y = m2; u.z = m3; u.w = m4;
            *(uint4*)(QT + ((qh * 128 + srow) << 2)) = u;
        }
        __syncthreads();

        // merge + exact refine (thread = row)
        if (tid < 128) {
            const int row = tid;
            const int grow = tile * ROWSB + row;
            int bi = 0;
            if (grow < n) {
                uint4 a = *(const uint4*)(QT + (row << 2));
                uint4 b = *(const uint4*)(QT + ((128 + row) << 2));
                uint32_t v[8] = { a.x, a.y, a.z, a.w, b.x, b.y, b.z, b.w };
                uint32_t mg = v[0];
                #pragma unroll
                for (int i = 1; i < 8; ++i) mg = umn(mg, v[i]);
                const uint32_t lim = mg + MARG_P;

                // x row + exact xs (reference rounding)
                float4 f[16];
                const float4* xr = (const float4*)(x + (size_t)grow * DD);
                #pragma unroll
                for (int k4 = 0; k4 < 16; ++k4) f[k4] = __ldg(xr + k4);
                float xs = 0.0f;
                #pragma unroll
                for (int k4 = 0; k4 < 16; ++k4) {
                    xs = __fadd_rn(xs, __fmul_rn(f[k4].x, f[k4].x));
                    xs = __fadd_rn(xs, __fmul_rn(f[k4].y, f[k4].y));
                    xs = __fadd_rn(xs, __fmul_rn(f[k4].z, f[k4].z));
                    xs = __fadd_rn(xs, __fmul_rn(f[k4].w, f[k4].w));
                }

                float best = 3.4e38f; bi = 0x7FFFFFFF;
                const bool fb = (a.w <= lim) || (b.w <= lim);  // >4 candidates in a half: exact rescan
                if (fb) {
                    for (int code = 0; code < KC; ++code) {
                        const float4* cr = (const float4*)(cbk + code * DD);
                        float dot = 0.0f;
                        #pragma unroll
                        for (int k4 = 0; k4 < 16; ++k4) {
                            float4 bb = __ldg(cr + k4);
                            dot = __fmaf_rn(f[k4].x, bb.x, dot);
                            dot = __fmaf_rn(f[k4].y, bb.y, dot);
                            dot = __fmaf_rn(f[k4].z, bb.z, dot);
                            dot = __fmaf_rn(f[k4].w, bb.w, dot);
                        }
                        float d = __fmaf_rn(-2.0f, dot, __fadd_rn(xs, Cs[code]));
                        if (d < best) { best = d; bi = code; }   // ascending: strict < = lowest-index ties
                    }
                } else {
                    #pragma unroll
                    for (int i = 0; i < 8; ++i) {
                        if (v[i] <= lim) {
                            const int code = (int)(v[i] & 511u);
                            const float4* cr = (const float4*)(cbk + code * DD);
                            float dot = 0.0f;
                            #pragma unroll
                            for (int k4 = 0; k4 < 16; ++k4) {
                                float4 bb = __ldg(cr + k4);
                                dot = __fmaf_rn(f[k4].x, bb.x, dot);
                                dot = __fmaf_rn(f[k4].y, bb.y, dot);
                                dot = __fmaf_rn(f[k4].z, bb.z, dot);
                                dot = __fmaf_rn(f[k4].w, bb.w, dot);
                            }
                            float t = __fadd_rn(xs, Cs[code]);
                            float d = __fmaf_rn(-2.0f, dot, t);
                            if (d < best || (d == best && code < bi)) { best = d; bi = code; }
                        }
                    }
                }
                out[2 * nD + grow] = (float)bi;
            }
            sidx[row] = bi;
        }
        __syncthreads();

        // gather z_q_x / z_q_x_bar
        for (int i = tid; i < ROWSB * 32; i += NTHR) {
            const int row = i >> 5;
            const int d = (i >> 4) & 1;
            const int q = i & 15;
            const int g = tile * ROWSB + row;
            if (g < n) {
                float4 v = __ldg(((const float4*)cbk) + sidx[row] * 16 + q);
                ((float4*)(out + (size_t)d * nD + (size_t)g * DD))[q] = v;
            }
        }
    }

    __syncthreads();
    if (wid == 0) tmem_dealloc(tmem, 256);

#else
    // ============ generic-arch fallback (compile-only on GB300) ============
    for (int c = tid; c < KC; c += NTHR) {
        float s = 0.0f;
        const float* cr = cbk + c * DD;
        for (int k = 0; k < DD; ++k) {
            float v = cr[k];
            s = __fadd_rn(s, __fmul_rn(v, v));
        }
        Cs[c] = s;
    }
    __syncthreads();
    for (long long row = (long long)bid * NTHR + tid; row < n; row += (long long)gridDim.x * NTHR) {
        const float* xr = x + row * DD;
        float xv[DD];
        for (int k = 0; k < DD; ++k) xv[k] = xr[k];
        float xs = 0.0f;
        for (int k = 0; k < DD; ++k) xs = __fadd_rn(xs, __fmul_rn(xv[k], xv[k]));
        float best = 3.4e38f; int bi = 0;
        for (int c = 0; c < KC; ++c) {
            const float* cr = cbk + c * DD;
            float dot = 0.0f;
            for (int k = 0; k < DD; ++k) dot = __fmaf_rn(xv[k], cr[k], dot);
            float d = __fmaf_rn(-2.0f, dot, __fadd_rn(xs, Cs[c]));
            if (d < best) { best = d; bi = c; }
        }
        out[2 * nD + row] = (float)bi;
        const float* cr = cbk + bi * DD;
        for (int k = 0; k < DD; ++k) {
            out[(size_t)row * DD + k] = cr[k];
            out[nD + (size_t)row * DD + k] = cr[k];
        }
    }
#endif
}

extern "C" void kernel_launch(void* const* d_in, const int* in_sizes, int n_in,
                              void* d_out, int out_size) {
    const float* x = (const float*)d_in[0];
    const float* cbk = (const float*)d_in[1];
    float* out = (float*)d_out;
    const int n = in_sizes[0] / DD;

    cudaFuncSetAttribute(vq_persist, cudaFuncAttributeMaxDynamicSharedMemorySize, SMEM_TOTAL);
    vq_persist<<<NCTA, NTHR, SMEM_TOTAL>>>(x, cbk, out, n);
}

// round 10
// speedup vs baseline: 5.5503x; 5.5503x over previous
#include <cuda_runtime.h>
#include <cuda_bf16.h>
#include <cstdint>

#define DD 64
#define KC 512
#define ROWSB 128
#define NTHR 512
#define NCTA 148
#define MARG_P 22000u       // 2e-5 dist margin * 2^21 * 512
#define SCALE 2097152.0f    // 2^21
#define NEG2SCALE -4194304.0f

#if defined(__CUDA_ARCH__) && (defined(__CUDA_ARCH_FEAT_SM103_ALL) || defined(__CUDA_ARCH_FEAT_SM100_ALL) || defined(__CUDA_ARCH_FEAT_SM101_ALL))
#define HAS_TCGEN05 1
#else
#define HAS_TCGEN05 0
#endif

// ---- smem byte offsets ----
#define MB_MDONE   0
#define TMEM_SLOT  16
#define CS_OFF     128                 // 512 f32 exact csq
#define PRE_OFF    2176                // 512 f32 (csq+2)*2^21
#define XS_OFF     4224                // 2 x 128 f32
#define BD_OFF     5248                // 4 x 128 f32 exact best per (group,row)
#define BI_OFF     7296                // 4 x 128 i32
#define SIDX_OFF   9344                // 128 i32
#define A_OFF(b,s) (10240 + ((b) * 2 + (s)) * 16384)   // 2 bufs x {h,l}
#define B_OFF(s)   (76800 + (s) * 65536)               // {h,l} 64KB each, SW128
#define SMEM_TOTAL 208896

__device__ __forceinline__ uint32_t smem_u32(const void* p) {
    uint32_t a;
    asm("{ .reg .u64 t; cvta.to.shared.u64 t, %1; cvt.u32.u64 %0, t; }" : "=r"(a) : "l"(p));
    return a;
}
__device__ __forceinline__ uint32_t sw128(uint32_t off) { return off ^ ((off >> 3) & 0x70); }

#if HAS_TCGEN05
__device__ __forceinline__ uint32_t elect1() {
    uint32_t p;
    asm volatile("{ .reg .pred p; elect.sync _|p, 0xFFFFFFFF; selp.b32 %0, 1, 0, p; }" : "=r"(p));
    return p;
}
__device__ __forceinline__ void mbar_init(uint32_t a, uint32_t cnt) {
    asm volatile("mbarrier.init.shared.b64 [%0], %1;" :: "r"(a), "r"(cnt) : "memory");
}
__device__ __forceinline__ void mbar_wait(uint32_t a, uint32_t parity) {
    asm volatile(
        "{\n\t.reg .pred P;\n"
        "WL_%=:\n\t"
        "mbarrier.try_wait.parity.acquire.cta.shared::cta.b64 P, [%0], %1, 0x989680;\n\t"
        "@!P bra WL_%=;\n\t}"
        :: "r"(a), "r"(parity) : "memory");
}
__device__ __forceinline__ void fence_async() {
    asm volatile("fence.proxy.async.shared::cta;" ::: "memory");
}
__device__ __forceinline__ void tmem_alloc(uint32_t slot, uint32_t ncols) {
    asm volatile("tcgen05.alloc.cta_group::1.sync.aligned.shared::cta.b32 [%0], %1;"
                 :: "r"(slot), "r"(ncols) : "memory");
}
__device__ __forceinline__ void tmem_dealloc(uint32_t base, uint32_t ncols) {
    asm volatile("tcgen05.dealloc.cta_group::1.sync.aligned.b32 %0, %1;" :: "r"(base), "r"(ncols));
}
__device__ __forceinline__ void mma_f16_ss(uint32_t d, uint64_t ad, uint64_t bd,
                                           uint32_t idesc, uint32_t en) {
    asm volatile(
        "{\n\t.reg .pred p;\n\t"
        "setp.ne.u32 p, %5, 0;\n\t"
        "tcgen05.mma.cta_group::1.kind::f16 [%0], %1, %2, %3, {%4, %4, %4, %4}, p;\n\t}"
        :: "r"(d), "l"(ad), "l"(bd), "r"(idesc), "r"(0u), "r"(en) : "memory");
}
__device__ __forceinline__ void mma_commit(uint32_t mbar) {
    asm volatile("tcgen05.commit.cta_group::1.mbarrier::arrive::one.shared::cluster.b64 [%0];"
                 :: "r"(mbar) : "memory");
}
__device__ __forceinline__ void fence_tc_after() {
    asm volatile("tcgen05.fence::after_thread_sync;" ::: "memory");
}
__device__ __forceinline__ void fence_tc_before() {
    asm volatile("tcgen05.fence::before_thread_sync;" ::: "memory");
}
#define LDTM_X32(r, a) \
    asm volatile("tcgen05.ld.sync.aligned.32x32b.x32.b32 " \
        "{%0,%1,%2,%3,%4,%5,%6,%7,%8,%9,%10,%11,%12,%13,%14,%15," \
        "%16,%17,%18,%19,%20,%21,%22,%23,%24,%25,%26,%27,%28,%29,%30,%31}, [%32];" \
        : "=r"((r)[0]),"=r"((r)[1]),"=r"((r)[2]),"=r"((r)[3]),"=r"((r)[4]),"=r"((r)[5]), \
          "=r"((r)[6]),"=r"((r)[7]),"=r"((r)[8]),"=r"((r)[9]),"=r"((r)[10]),"=r"((r)[11]), \
          "=r"((r)[12]),"=r"((r)[13]),"=r"((r)[14]),"=r"((r)[15]),"=r"((r)[16]),"=r"((r)[17]), \
          "=r"((r)[18]),"=r"((r)[19]),"=r"((r)[20]),"=r"((r)[21]),"=r"((r)[22]),"=r"((r)[23]), \
          "=r"((r)[24]),"=r"((r)[25]),"=r"((r)[26]),"=r"((r)[27]),"=r"((r)[28]),"=r"((r)[29]), \
          "=r"((r)[30]),"=r"((r)[31]) : "r"(a))
__device__ __forceinline__ void tmem_wait_ld() {
    asm volatile("tcgen05.wait::ld.sync.aligned;" ::: "memory");
}
#endif

#define DESC_BASE 0x4000404000010000ULL
__device__ __forceinline__ uint64_t mk_desc(uint32_t addr) {
    return DESC_BASE | ((uint64_t)(addr >> 4) & 0x3FFF);
}
#define IDESC 0x8200490u   // f32 acc, bf16 a/b, M=128, N=128 (proven R3-R9)

__device__ __forceinline__ uint32_t packbf(float a, float b) {
    return (uint32_t)__bfloat16_as_ushort(__float2bfloat16(a)) |
           ((uint32_t)__bfloat16_as_ushort(__float2bfloat16(b)) << 16);
}
__device__ __forceinline__ uint32_t umn(uint32_t a, uint32_t b) { return a < b ? a : b; }
__device__ __forceinline__ uint32_t umx(uint32_t a, uint32_t b) { return a > b ? a : b; }

__global__ void __launch_bounds__(NTHR, 1)
vq_persist(const float* __restrict__ x, const float* __restrict__ cbk,
           float* __restrict__ out, int n) {
    extern __shared__ char smem[];
    const int tid = threadIdx.x;
    const int bid = blockIdx.x;
    const size_t nD = (size_t)n * DD;
    float* Cs = (float*)(smem + CS_OFF);

#if HAS_TCGEN05
    const uint32_t sb = smem_u32(smem);
    const int wid = tid >> 5;
    const int lane = tid & 31;
    float* pre = (float*)(smem + PRE_OFF);
    float* XsS = (float*)(smem + XS_OFF);
    float* BD = (float*)(smem + BD_OFF);
    int* BI = (int*)(smem + BI_OFF);
    int* sidx = (int*)(smem + SIDX_OFF);

    const int ntiles = (n + ROWSB - 1) / ROWSB;
    const int nt = (ntiles > bid) ? (ntiles - bid + NCTA - 1) / NCTA : 0;

    // ---------- startup ----------
    if (tid == 0) mbar_init(sb + MB_MDONE, 1);
    if (wid == 0) tmem_alloc(sb + TMEM_SLOT, 512);

    // B limbs: 512x64 -> bf16 h,l SW128 (128B per code row each)
    for (int i = tid; i < KC * DD / 4; i += NTHR) {
        int code = i >> 4, kq = i & 15;
        float4 v = __ldg(((const float4*)cbk) + i);
        __nv_bfloat16 hx = __float2bfloat16(v.x), hy = __float2bfloat16(v.y);
        __nv_bfloat16 hz = __float2bfloat16(v.z), hw = __float2bfloat16(v.w);
        uint64_t uh = (uint64_t)((uint32_t)__bfloat16_as_ushort(hx) |
                                 ((uint32_t)__bfloat16_as_ushort(hy) << 16)) |
                      ((uint64_t)((uint32_t)__bfloat16_as_ushort(hz) |
                                 ((uint32_t)__bfloat16_as_ushort(hw) << 16)) << 32);
        uint64_t ul = (uint64_t)packbf(v.x - __bfloat162float(hx), v.y - __bfloat162float(hy)) |
                      ((uint64_t)packbf(v.z - __bfloat162float(hz), v.w - __bfloat162float(hw)) << 32);
        uint32_t so = sw128(code * 128 + kq * 8);
        *(uint64_t*)(smem + B_OFF(0) + so) = uh;
        *(uint64_t*)(smem + B_OFF(1) + so) = ul;
    }
    // exact csq (reference rounding) + filter prescale
    for (int c = tid; c < KC; c += NTHR) {
        float s = 0.0f;
        const float* cr = cbk + c * DD;
        for (int k = 0; k < DD; ++k) {
            float v = __ldg(cr + k);
            s = __fadd_rn(s, __fmul_rn(v, v));
        }
        Cs[c] = s;
        pre[c] = (s + 2.0f) * SCALE;
    }
    // build A[0] (h,l) + xs for tile 0
    if (tid < 128 && nt > 0) {
        const int grow = bid * ROWSB + tid;
        float s = 0.0f;
        #pragma unroll
        for (int k4 = 0; k4 < 16; ++k4) {
            float4 v = make_float4(0.f, 0.f, 0.f, 0.f);
            if (grow < n) v = __ldg(((const float4*)(x + (size_t)grow * DD)) + k4);
            s = __fadd_rn(s, __fmul_rn(v.x, v.x));
            s = __fadd_rn(s, __fmul_rn(v.y, v.y));
            s = __fadd_rn(s, __fmul_rn(v.z, v.z));
            s = __fadd_rn(s, __fmul_rn(v.w, v.w));
            __nv_bfloat16 hx = __float2bfloat16(v.x), hy = __float2bfloat16(v.y);
            __nv_bfloat16 hz = __float2bfloat16(v.z), hw = __float2bfloat16(v.w);
            uint64_t uh = (uint64_t)((uint32_t)__bfloat16_as_ushort(hx) |
                                     ((uint32_t)__bfloat16_as_ushort(hy) << 16)) |
                          ((uint64_t)((uint32_t)__bfloat16_as_ushort(hz) |
                                     ((uint32_t)__bfloat16_as_ushort(hw) << 16)) << 32);
            uint64_t ul = (uint64_t)packbf(v.x - __bfloat162float(hx), v.y - __bfloat162float(hy)) |
                          ((uint64_t)packbf(v.z - __bfloat162float(hz), v.w - __bfloat162float(hw)) << 32);
            uint32_t so = sw128(tid * 128 + k4 * 8);
            *(uint64_t*)(smem + A_OFF(0, 0) + so) = uh;
            *(uint64_t*)(smem + A_OFF(0, 1) + so) = ul;
        }
        XsS[tid] = s;
    }
    fence_async();
    __syncthreads();
    const uint32_t tmem = *(volatile uint32_t*)(smem + TMEM_SLOT);

    const int sub = wid & 3;
    const int qh = wid >> 2;              // code quarter: cols [qh*128, qh*128+128)
    const int srow = sub * 32 + lane;
    const int cbase = qh * 128;
    const uint64_t bdh = mk_desc(sb + B_OFF(0));
    const uint64_t bdl = mk_desc(sb + B_OFF(1));

    // ---------- main loop (R7-proven monolithic skeleton) ----------
    for (int it = 0; it < nt; ++it) {
        const int buf = it & 1;
        const int tile = bid + it * NCTA;

        // 1) issue 48 MMAs: per quarter, 3 limb-products x 4 ksteps, one accumulator
        if (wid == 0) {
            if (elect1()) {
                const uint64_t adh = mk_desc(sb + A_OFF(buf, 0));
                const uint64_t adl = mk_desc(sb + A_OFF(buf, 1));
                for (int q = 0; q < 4; ++q) {
                    const uint32_t dcol = tmem + q * 128;
                    const uint32_t qo = (uint32_t)(q * 1024);
                    #pragma unroll
                    for (int k = 0; k < 4; ++k)
                        mma_f16_ss(dcol, adh + k * 2, bdh + qo + k * 2, IDESC, k != 0);
                    #pragma unroll
                    for (int k = 0; k < 4; ++k)
                        mma_f16_ss(dcol, adh + k * 2, bdl + qo + k * 2, IDESC, 1);
                    #pragma unroll
                    for (int k = 0; k < 4; ++k)
                        mma_f16_ss(dcol, adl + k * 2, bdh + qo + k * 2, IDESC, 1);
                }
                mma_commit(sb + MB_MDONE);
            }
        }

        // 2) build A for tile it+1 (overlaps MMA)
        if (tid < 128 && it + 1 < nt) {
            const int ab = (it + 1) & 1;
            const int grow2 = (bid + (it + 1) * NCTA) * ROWSB + tid;
            float s = 0.0f;
            #pragma unroll
            for (int k4 = 0; k4 < 16; ++k4) {
                float4 v = make_float4(0.f, 0.f, 0.f, 0.f);
                if (grow2 < n) v = __ldg(((const float4*)(x + (size_t)grow2 * DD)) + k4);
                s = __fadd_rn(s, __fmul_rn(v.x, v.x));
                s = __fadd_rn(s, __fmul_rn(v.y, v.y));
                s = __fadd_rn(s, __fmul_rn(v.z, v.z));
                s = __fadd_rn(s, __fmul_rn(v.w, v.w));
                __nv_bfloat16 hx = __float2bfloat16(v.x), hy = __float2bfloat16(v.y);
                __nv_bfloat16 hz = __float2bfloat16(v.z), hw = __float2bfloat16(v.w);
                uint64_t uh = (uint64_t)((uint32_t)__bfloat16_as_ushort(hx) |
                                         ((uint32_t)__bfloat16_as_ushort(hy) << 16)) |
                              ((uint64_t)((uint32_t)__bfloat16_as_ushort(hz) |
                                         ((uint32_t)__bfloat16_as_ushort(hw) << 16)) << 32);
                uint64_t ul = (uint64_t)packbf(v.x - __bfloat162float(hx), v.y - __bfloat162float(hy)) |
                              ((uint64_t)packbf(v.z - __bfloat162float(hz), v.w - __bfloat162float(hw)) << 32);
                uint32_t so = sw128(tid * 128 + k4 * 8);
                *(uint64_t*)(smem + A_OFF(ab, 0) + so) = uh;
                *(uint64_t*)(smem + A_OFF(ab, 1) + so) = ul;
            }
            XsS[ab * 128 + tid] = s;
            fence_async();
        }

        // 3) wait MMA (normally already complete)
        mbar_wait(sb + MB_MDONE, (uint32_t)(it & 1));
        fence_tc_after();

        // 4) branchless top-3 packed-key filter over (row srow, 128 codes)
        uint32_t m1 = 0xFFFFFFFFu, m2 = 0xFFFFFFFFu, m3 = 0xFFFFFFFFu;
        for (int b = 0; b < 4; ++b) {
            uint32_t rg[32];
            LDTM_X32(rg, tmem + cbase + b * 32);
            tmem_wait_ld();
            const int base = cbase + b * 32;
            #pragma unroll
            for (int j4 = 0; j4 < 8; ++j4) {
                float4 p4 = *(const float4*)(pre + base + j4 * 4);
                #pragma unroll
                for (int jj = 0; jj < 4; ++jj) {
                    float pv = (jj == 0) ? p4.x : (jj == 1) ? p4.y : (jj == 2) ? p4.z : p4.w;
                    float kf = __fmaf_rn(__uint_as_float(rg[j4 * 4 + jj]), NEG2SCALE, pv);
                    uint32_t pk = __float2uint_rz(kf) * 512u + (uint32_t)(base + j4 * 4 + jj);
                    uint32_t t1 = umx(m1, pk); m1 = umn(m1, pk);
                    uint32_t t2 = umx(m2, t1); m2 = umn(m2, t1);
                    m3 = umn(m3, t2);
                }
            }
        }
        fence_tc_before();

        // 5) per-thread exact refine (<=3 candidates; margin-gated)
        const int grow = tile * ROWSB + srow;
        float best = 3.4e38f; int bib = 0x7FFFFFFF;
        if (grow < n) {
            const float xs = XsS[buf * 128 + srow];
            const float4* xr = (const float4*)(x + (size_t)grow * DD);
            const uint32_t lim = m1 + MARG_P;
            uint32_t cand[3] = { m1, m2, m3 };
            #pragma unroll
            for (int i = 0; i < 3; ++i) {
                if (cand[i] <= lim) {
                    const int code = (int)(cand[i] & 511u);
                    const float4* cr = (const float4*)(cbk + code * DD);
                    float dot = 0.0f;
                    #pragma unroll
                    for (int k4 = 0; k4 < 16; ++k4) {
                        float4 a = __ldg(xr + k4);
                        float4 bb = __ldg(cr + k4);
                        dot = __fmaf_rn(a.x, bb.x, dot);
                        dot = __fmaf_rn(a.y, bb.y, dot);
                        dot = __fmaf_rn(a.z, bb.z, dot);
                        dot = __fmaf_rn(a.w, bb.w, dot);
                    }
                    float t = __fadd_rn(xs, Cs[code]);
                    float d = __fmaf_rn(-2.0f, dot, t);
                    if (d < best || (d == best && code < bib)) { best = d; bib = code; }
                }
            }
        }
        BD[qh * 128 + srow] = best;
        BI[qh * 128 + srow] = bib;
        __syncthreads();

        // 6) merge 4 quarters (exact dist, lowest-code ties) -> index output
        if (tid < 128) {
            float bd = BD[tid]; int bi = BI[tid];
            #pragma unroll
            for (int g = 1; g < 4; ++g) {
                float d = BD[g * 128 + tid]; int ii = BI[g * 128 + tid];
                if (d < bd || (d == bd && ii < bi)) { bd = d; bi = ii; }
            }
            sidx[tid] = bi;
            const int g = tile * ROWSB + tid;
            if (g < n) out[2 * nD + g] = (float)bi;
        }
        __syncthreads();

        // 7) gather z_q_x / z_q_x_bar
        for (int i = tid; i < ROWSB * 32; i += NTHR) {
            const int row = i >> 5;
            const int d = (i >> 4) & 1;
            const int q = i & 15;
            const int g = tile * ROWSB + row;
            if (g < n) {
                float4 v = __ldg(((const float4*)cbk) + sidx[row] * 16 + q);
                ((float4*)(out + (size_t)d * nD + (size_t)g * DD))[q] = v;
            }
        }
    }

    __syncthreads();
    if (wid == 0) tmem_dealloc(tmem, 512);

#else
    // ============ generic-arch fallback (compile-only on GB300) ============
    for (int c = tid; c < KC; c += NTHR) {
        float s = 0.0f;
        const float* cr = cbk + c * DD;
        for (int k = 0; k < DD; ++k) {
            float v = cr[k];
            s = __fadd_rn(s, __fmul_rn(v, v));
        }
        Cs[c] = s;
    }
    __syncthreads();
    for (long long row = (long long)bid * NTHR + tid; row < n; row += (long long)gridDim.x * NTHR) {
        const float* xr = x + row * DD;
        float xv[DD];
        for (int k = 0; k < DD; ++k) xv[k] = xr[k];
        float xs = 0.0f;
        for (int k = 0; k < DD; ++k) xs = __fadd_rn(xs, __fmul_rn(xv[k], xv[k]));
        float best = 3.4e38f; int bi = 0;
        for (int c = 0; c < KC; ++c) {
            const float* cr = cbk + c * DD;
            float dot = 0.0f;
            for (int k = 0; k < DD; ++k) dot = __fmaf_rn(xv[k], cr[k], dot);
            float d = __fmaf_rn(-2.0f, dot, __fadd_rn(xs, Cs[c]));
            if (d < best) { best = d; bi = c; }
        }
        out[2 * nD + row] = (float)bi;
        const float* cr = cbk + bi * DD;
        for (int k = 0; k < DD; ++k) {
            out[(size_t)row * DD + k] = cr[k];
            out[nD + (size_t)row * DD + k] = cr[k];
        }
    }
#endif
}

extern "C" void kernel_launch(void* const* d_in, const int* in_sizes, int n_in,
                              void* d_out, int out_size) {
    const float* x = (const float*)d_in[0];
    const float* cbk = (const float*)d_in[1];
    float* out = (float*)d_out;
    const int n = in_sizes[0] / DD;

    cudaFuncSetAttribute(vq_persist, cudaFuncAttributeMaxDynamicSharedMemorySize, SMEM_TOTAL);
    vq_persist<<<NCTA, NTHR, SMEM_TOTAL>>>(x, cbk, out, n);
}

// round 11
// speedup vs baseline: 9.1744x; 1.6529x over previous
#include <cuda_runtime.h>
#include <cuda_bf16.h>
#include <cstdint>

#define DD 64
#define KC 512
#define ROWSB 128
#define NTHR 512
#define NCTA 148
#define MARG_P 22000u       // 2e-5 dist margin * 2^21 * 512
#define SCALE 2097152.0f    // 2^21
#define NEG2SCALE -4194304.0f

#if defined(__CUDA_ARCH__) && (defined(__CUDA_ARCH_FEAT_SM103_ALL) || defined(__CUDA_ARCH_FEAT_SM100_ALL) || defined(__CUDA_ARCH_FEAT_SM101_ALL))
#define HAS_TCGEN05 1
#else
#define HAS_TCGEN05 0
#endif

// ---- smem byte offsets ----
#define MB_MDONE   0
#define TMEM_SLOT  16
#define CS_OFF     128                 // 512 f32 exact csq
#define PRE_OFF    2176                // 512 f32 (csq+2)*2^21
#define XS_OFF     4224                // 2 x 128 f32
#define QT_OFF     5248                // 512 threads x uint4 (top-3 keys)
#define SIDX_OFF   13440               // 128 i32
#define A_OFF(b,s) (14336 + ((b) * 2 + (s)) * 16384)   // 2 bufs x {h,l}
#define B_OFF(s)   (79872 + (s) * 65536)               // {h,l} 64KB each, SW128
#define SMEM_TOTAL 210944

__device__ __forceinline__ uint32_t smem_u32(const void* p) {
    uint32_t a;
    asm("{ .reg .u64 t; cvta.to.shared.u64 t, %1; cvt.u32.u64 %0, t; }" : "=r"(a) : "l"(p));
    return a;
}
__device__ __forceinline__ uint32_t sw128(uint32_t off) { return off ^ ((off >> 3) & 0x70); }

#if HAS_TCGEN05
__device__ __forceinline__ uint32_t elect1() {
    uint32_t p;
    asm volatile("{ .reg .pred p; elect.sync _|p, 0xFFFFFFFF; selp.b32 %0, 1, 0, p; }" : "=r"(p));
    return p;
}
__device__ __forceinline__ void mbar_init(uint32_t a, uint32_t cnt) {
    asm volatile("mbarrier.init.shared.b64 [%0], %1;" :: "r"(a), "r"(cnt) : "memory");
}
__device__ __forceinline__ void mbar_wait(uint32_t a, uint32_t parity) {
    asm volatile(
        "{\n\t.reg .pred P;\n"
        "WL_%=:\n\t"
        "mbarrier.try_wait.parity.acquire.cta.shared::cta.b64 P, [%0], %1, 0x989680;\n\t"
        "@!P bra WL_%=;\n\t}"
        :: "r"(a), "r"(parity) : "memory");
}
__device__ __forceinline__ void fence_async() {
    asm volatile("fence.proxy.async.shared::cta;" ::: "memory");
}
__device__ __forceinline__ void tmem_alloc(uint32_t slot, uint32_t ncols) {
    asm volatile("tcgen05.alloc.cta_group::1.sync.aligned.shared::cta.b32 [%0], %1;"
                 :: "r"(slot), "r"(ncols) : "memory");
}
__device__ __forceinline__ void tmem_dealloc(uint32_t base, uint32_t ncols) {
    asm volatile("tcgen05.dealloc.cta_group::1.sync.aligned.b32 %0, %1;" :: "r"(base), "r"(ncols));
}
__device__ __forceinline__ void mma_f16_ss(uint32_t d, uint64_t ad, uint64_t bd,
                                           uint32_t idesc, uint32_t en) {
    asm volatile(
        "{\n\t.reg .pred p;\n\t"
        "setp.ne.u32 p, %5, 0;\n\t"
        "tcgen05.mma.cta_group::1.kind::f16 [%0], %1, %2, %3, {%4, %4, %4, %4}, p;\n\t}"
        :: "r"(d), "l"(ad), "l"(bd), "r"(idesc), "r"(0u), "r"(en) : "memory");
}
__device__ __forceinline__ void mma_commit(uint32_t mbar) {
    asm volatile("tcgen05.commit.cta_group::1.mbarrier::arrive::one.shared::cluster.b64 [%0];"
                 :: "r"(mbar) : "memory");
}
__device__ __forceinline__ void fence_tc_after() {
    asm volatile("tcgen05.fence::after_thread_sync;" ::: "memory");
}
__device__ __forceinline__ void fence_tc_before() {
    asm volatile("tcgen05.fence::before_thread_sync;" ::: "memory");
}
#define LDTM_X32(r, a) \
    asm volatile("tcgen05.ld.sync.aligned.32x32b.x32.b32 " \
        "{%0,%1,%2,%3,%4,%5,%6,%7,%8,%9,%10,%11,%12,%13,%14,%15," \
        "%16,%17,%18,%19,%20,%21,%22,%23,%24,%25,%26,%27,%28,%29,%30,%31}, [%32];" \
        : "=r"((r)[0]),"=r"((r)[1]),"=r"((r)[2]),"=r"((r)[3]),"=r"((r)[4]),"=r"((r)[5]), \
          "=r"((r)[6]),"=r"((r)[7]),"=r"((r)[8]),"=r"((r)[9]),"=r"((r)[10]),"=r"((r)[11]), \
          "=r"((r)[12]),"=r"((r)[13]),"=r"((r)[14]),"=r"((r)[15]),"=r"((r)[16]),"=r"((r)[17]), \
          "=r"((r)[18]),"=r"((r)[19]),"=r"((r)[20]),"=r"((r)[21]),"=r"((r)[22]),"=r"((r)[23]), \
          "=r"((r)[24]),"=r"((r)[25]),"=r"((r)[26]),"=r"((r)[27]),"=r"((r)[28]),"=r"((r)[29]), \
          "=r"((r)[30]),"=r"((r)[31]) : "r"(a))
__device__ __forceinline__ void tmem_wait_ld() {
    asm volatile("tcgen05.wait::ld.sync.aligned;" ::: "memory");
}
#endif

#define DESC_BASE 0x4000404000010000ULL
__device__ __forceinline__ uint64_t mk_desc(uint32_t addr) {
    return DESC_BASE | ((uint64_t)(addr >> 4) & 0x3FFF);
}
#define IDESC 0x8200490u   // f32 acc, bf16 a/b, M=128, N=128 (proven R3-R10)

__device__ __forceinline__ uint32_t packbf(float a, float b) {
    return (uint32_t)__bfloat16_as_ushort(__float2bfloat16(a)) |
           ((uint32_t)__bfloat16_as_ushort(__float2bfloat16(b)) << 16);
}
__device__ __forceinline__ uint32_t umn(uint32_t a, uint32_t b) { return a < b ? a : b; }
__device__ __forceinline__ uint32_t umx(uint32_t a, uint32_t b) { return a > b ? a : b; }

__global__ void __launch_bounds__(NTHR, 1)
vq_persist(const float* __restrict__ x, const float* __restrict__ cbk,
           float* __restrict__ out, int n) {
    extern __shared__ char smem[];
    const int tid = threadIdx.x;
    const int bid = blockIdx.x;
    const size_t nD = (size_t)n * DD;
    float* Cs = (float*)(smem + CS_OFF);

#if HAS_TCGEN05
    const uint32_t sb = smem_u32(smem);
    const int wid = tid >> 5;
    const int lane = tid & 31;
    float* pre = (float*)(smem + PRE_OFF);
    float* XsS = (float*)(smem + XS_OFF);
    uint32_t* QT = (uint32_t*)(smem + QT_OFF);
    int* sidx = (int*)(smem + SIDX_OFF);

    const int ntiles = (n + ROWSB - 1) / ROWSB;
    const int nt = (ntiles > bid) ? (ntiles - bid + NCTA - 1) / NCTA : 0;

    // ---------- startup ----------
    if (tid == 0) mbar_init(sb + MB_MDONE, 1);
    if (wid == 0) tmem_alloc(sb + TMEM_SLOT, 512);

    // B limbs: 512x64 -> bf16 h,l SW128 (128B per code row each)
    for (int i = tid; i < KC * DD / 4; i += NTHR) {
        int code = i >> 4, kq = i & 15;
        float4 v = __ldg(((const float4*)cbk) + i);
        __nv_bfloat16 hx = __float2bfloat16(v.x), hy = __float2bfloat16(v.y);
        __nv_bfloat16 hz = __float2bfloat16(v.z), hw = __float2bfloat16(v.w);
        uint64_t uh = (uint64_t)((uint32_t)__bfloat16_as_ushort(hx) |
                                 ((uint32_t)__bfloat16_as_ushort(hy) << 16)) |
                      ((uint64_t)((uint32_t)__bfloat16_as_ushort(hz) |
                                 ((uint32_t)__bfloat16_as_ushort(hw) << 16)) << 32);
        uint64_t ul = (uint64_t)packbf(v.x - __bfloat162float(hx), v.y - __bfloat162float(hy)) |
                      ((uint64_t)packbf(v.z - __bfloat162float(hz), v.w - __bfloat162float(hw)) << 32);
        uint32_t so = sw128(code * 128 + kq * 8);
        *(uint64_t*)(smem + B_OFF(0) + so) = uh;
        *(uint64_t*)(smem + B_OFF(1) + so) = ul;
    }
    // exact csq (reference rounding) + filter prescale
    for (int c = tid; c < KC; c += NTHR) {
        float s = 0.0f;
        const float* cr = cbk + c * DD;
        for (int k = 0; k < DD; ++k) {
            float v = __ldg(cr + k);
            s = __fadd_rn(s, __fmul_rn(v, v));
        }
        Cs[c] = s;
        pre[c] = (s + 2.0f) * SCALE;
    }
    // build A[0] (h,l) + xs for tile 0
    if (tid < 128 && nt > 0) {
        const int grow = bid * ROWSB + tid;
        float s = 0.0f;
        #pragma unroll
        for (int k4 = 0; k4 < 16; ++k4) {
            float4 v = make_float4(0.f, 0.f, 0.f, 0.f);
            if (grow < n) v = __ldg(((const float4*)(x + (size_t)grow * DD)) + k4);
            s = __fadd_rn(s, __fmul_rn(v.x, v.x));
            s = __fadd_rn(s, __fmul_rn(v.y, v.y));
            s = __fadd_rn(s, __fmul_rn(v.z, v.z));
            s = __fadd_rn(s, __fmul_rn(v.w, v.w));
            __nv_bfloat16 hx = __float2bfloat16(v.x), hy = __float2bfloat16(v.y);
            __nv_bfloat16 hz = __float2bfloat16(v.z), hw = __float2bfloat16(v.w);
            uint64_t uh = (uint64_t)((uint32_t)__bfloat16_as_ushort(hx) |
                                     ((uint32_t)__bfloat16_as_ushort(hy) << 16)) |
                          ((uint64_t)((uint32_t)__bfloat16_as_ushort(hz) |
                                     ((uint32_t)__bfloat16_as_ushort(hw) << 16)) << 32);
            uint64_t ul = (uint64_t)packbf(v.x - __bfloat162float(hx), v.y - __bfloat162float(hy)) |
                          ((uint64_t)packbf(v.z - __bfloat162float(hz), v.w - __bfloat162float(hw)) << 32);
            uint32_t so = sw128(tid * 128 + k4 * 8);
            *(uint64_t*)(smem + A_OFF(0, 0) + so) = uh;
            *(uint64_t*)(smem + A_OFF(0, 1) + so) = ul;
        }
        XsS[tid] = s;
    }
    fence_async();
    __syncthreads();
    const uint32_t tmem = *(volatile uint32_t*)(smem + TMEM_SLOT);

    const int sub = wid & 3;
    const int qh = wid >> 2;              // code quarter: cols [qh*128, qh*128+128)
    const int srow = sub * 32 + lane;
    const int cbase = qh * 128;
    const uint64_t bdh = mk_desc(sb + B_OFF(0));
    const uint64_t bdl = mk_desc(sb + B_OFF(1));

    // ---------- main loop (R7/R10-proven monolithic skeleton) ----------
    for (int it = 0; it < nt; ++it) {
        const int buf = it & 1;
        const int tile = bid + it * NCTA;

        // 1) issue 48 MMAs: per quarter, 3 limb-products x 4 ksteps, one accumulator
        if (wid == 0) {
            if (elect1()) {
                const uint64_t adh = mk_desc(sb + A_OFF(buf, 0));
                const uint64_t adl = mk_desc(sb + A_OFF(buf, 1));
                for (int q = 0; q < 4; ++q) {
                    const uint32_t dcol = tmem + q * 128;
                    const uint32_t qo = (uint32_t)(q * 1024);
                    #pragma unroll
                    for (int k = 0; k < 4; ++k)
                        mma_f16_ss(dcol, adh + k * 2, bdh + qo + k * 2, IDESC, k != 0);
                    #pragma unroll
                    for (int k = 0; k < 4; ++k)
                        mma_f16_ss(dcol, adh + k * 2, bdl + qo + k * 2, IDESC, 1);
                    #pragma unroll
                    for (int k = 0; k < 4; ++k)
                        mma_f16_ss(dcol, adl + k * 2, bdh + qo + k * 2, IDESC, 1);
                }
                mma_commit(sb + MB_MDONE);
            }
        }

        // 2) build A for tile it+1 (overlaps MMA)
        if (tid < 128 && it + 1 < nt) {
            const int ab = (it + 1) & 1;
            const int grow2 = (bid + (it + 1) * NCTA) * ROWSB + tid;
            float s = 0.0f;
            #pragma unroll
            for (int k4 = 0; k4 < 16; ++k4) {
                float4 v = make_float4(0.f, 0.f, 0.f, 0.f);
                if (grow2 < n) v = __ldg(((const float4*)(x + (size_t)grow2 * DD)) + k4);
                s = __fadd_rn(s, __fmul_rn(v.x, v.x));
                s = __fadd_rn(s, __fmul_rn(v.y, v.y));
                s = __fadd_rn(s, __fmul_rn(v.z, v.z));
                s = __fadd_rn(s, __fmul_rn(v.w, v.w));
                __nv_bfloat16 hx = __float2bfloat16(v.x), hy = __float2bfloat16(v.y);
                __nv_bfloat16 hz = __float2bfloat16(v.z), hw = __float2bfloat16(v.w);
                uint64_t uh = (uint64_t)((uint32_t)__bfloat16_as_ushort(hx) |
                                         ((uint32_t)__bfloat16_as_ushort(hy) << 16)) |
                              ((uint64_t)((uint32_t)__bfloat16_as_ushort(hz) |
                                         ((uint32_t)__bfloat16_as_ushort(hw) << 16)) << 32);
                uint64_t ul = (uint64_t)packbf(v.x - __bfloat162float(hx), v.y - __bfloat162float(hy)) |
                              ((uint64_t)packbf(v.z - __bfloat162float(hz), v.w - __bfloat162float(hw)) << 32);
                uint32_t so = sw128(tid * 128 + k4 * 8);
                *(uint64_t*)(smem + A_OFF(ab, 0) + so) = uh;
                *(uint64_t*)(smem + A_OFF(ab, 1) + so) = ul;
            }
            XsS[ab * 128 + tid] = s;
            fence_async();
        }

        // 3) wait MMA (normally already complete)
        mbar_wait(sb + MB_MDONE, (uint32_t)(it & 1));
        fence_tc_after();

        // 4) branchless top-3 packed-key filter, software-pipelined LDTM
        uint32_t m1 = 0xFFFFFFFFu, m2 = 0xFFFFFFFFu, m3 = 0xFFFFFFFFu;
        {
            uint32_t rgA[32], rgB[32];
            LDTM_X32(rgA, tmem + cbase);
            tmem_wait_ld();
            #pragma unroll
            for (int b = 0; b < 4; ++b) {
                const uint32_t* cur = (b & 1) ? rgB : rgA;
                uint32_t* nxt = (b & 1) ? rgA : rgB;
                if (b < 3) LDTM_X32(nxt, tmem + cbase + (b + 1) * 32);
                const int base = cbase + b * 32;
                #pragma unroll
                for (int j4 = 0; j4 < 8; ++j4) {
                    float4 p4 = *(const float4*)(pre + base + j4 * 4);
                    #pragma unroll
                    for (int jj = 0; jj < 4; ++jj) {
                        float pv = (jj == 0) ? p4.x : (jj == 1) ? p4.y : (jj == 2) ? p4.z : p4.w;
                        float kf = __fmaf_rn(__uint_as_float(cur[j4 * 4 + jj]), NEG2SCALE, pv);
                        uint32_t pk = __float2uint_rz(kf) * 512u + (uint32_t)(base + j4 * 4 + jj);
                        uint32_t t1 = umx(m1, pk); m1 = umn(m1, pk);
                        uint32_t t2 = umx(m2, t1); m2 = umn(m2, t1);
                        m3 = umn(m3, t2);
                    }
                }
                if (b < 3) tmem_wait_ld();
            }
        }
        fence_tc_before();
        {
            uint4 u; u.x = m1; u.y = m2; u.z = m3; u.w = 0xFFFFFFFFu;
            *(uint4*)(QT + ((qh * 128 + srow) << 2)) = u;
        }
        __syncthreads();

        // 5) merge 12 keys per row, exact-refine survivors once (thread = row)
        if (tid < 128) {
            const int row = tid;
            const int grow = tile * ROWSB + row;
            int bib = 0;
            if (grow < n) {
                uint4 q0 = *(const uint4*)(QT + (row << 2));
                uint4 q1 = *(const uint4*)(QT + ((128 + row) << 2));
                uint4 q2 = *(const uint4*)(QT + ((256 + row) << 2));
                uint4 q3 = *(const uint4*)(QT + ((384 + row) << 2));
                uint32_t v[12] = { q0.x, q0.y, q0.z, q1.x, q1.y, q1.z,
                                   q2.x, q2.y, q2.z, q3.x, q3.y, q3.z };
                uint32_t gmin = v[0];
                #pragma unroll
                for (int i = 1; i < 12; ++i) gmin = umn(gmin, v[i]);
                const uint32_t lim = gmin + MARG_P;
                const float xs = XsS[buf * 128 + row];
                const float4* xr = (const float4*)(x + (size_t)grow * DD);
                float best = 3.4e38f; bib = 0x7FFFFFFF;
                // safety: if any quarter's 3rd-best is within lim, a 4th might be hidden
                const bool fb = (q0.z <= lim) || (q1.z <= lim) || (q2.z <= lim) || (q3.z <= lim);
                if (fb) {
                    for (int code = 0; code < KC; ++code) {
                        const float4* cr = (const float4*)(cbk + code * DD);
                        float dot = 0.0f;
                        #pragma unroll
                        for (int k4 = 0; k4 < 16; ++k4) {
                            float4 a = __ldg(xr + k4);
                            float4 bb = __ldg(cr + k4);
                            dot = __fmaf_rn(a.x, bb.x, dot);
                            dot = __fmaf_rn(a.y, bb.y, dot);
                            dot = __fmaf_rn(a.z, bb.z, dot);
                            dot = __fmaf_rn(a.w, bb.w, dot);
                        }
                        float d = __fmaf_rn(-2.0f, dot, __fadd_rn(xs, Cs[code]));
                        if (d < best) { best = d; bib = code; }  // ascending: lowest-index ties
                    }
                } else {
                    #pragma unroll
                    for (int i = 0; i < 12; ++i) {
                        if (v[i] <= lim) {
                            const int code = (int)(v[i] & 511u);
                            const float4* cr = (const float4*)(cbk + code * DD);
                            float dot = 0.0f;
                            #pragma unroll
                            for (int k4 = 0; k4 < 16; ++k4) {
                                float4 a = __ldg(xr + k4);
                                float4 bb = __ldg(cr + k4);
                                dot = __fmaf_rn(a.x, bb.x, dot);
                                dot = __fmaf_rn(a.y, bb.y, dot);
                                dot = __fmaf_rn(a.z, bb.z, dot);
                                dot = __fmaf_rn(a.w, bb.w, dot);
                            }
                            float t = __fadd_rn(xs, Cs[code]);
                            float d = __fmaf_rn(-2.0f, dot, t);
                            if (d < best || (d == best && code < bib)) { best = d; bib = code; }
                        }
                    }
                }
                out[2 * nD + grow] = (float)bib;
            }
            sidx[row] = bib;
        }
        __syncthreads();

        // 6) gather z_q_x / z_q_x_bar (overlaps next iter's MMA issue + A build)
        for (int i = tid; i < ROWSB * 32; i += NTHR) {
            const int row = i >> 5;
            const int d = (i >> 4) & 1;
            const int q = i & 15;
            const int g = tile * ROWSB + row;
            if (g < n) {
                float4 v = __ldg(((const float4*)cbk) + sidx[row] * 16 + q);
                ((float4*)(out + (size_t)d * nD + (size_t)g * DD))[q] = v;
            }
        }
    }

    __syncthreads();
    if (wid == 0) tmem_dealloc(tmem, 512);

#else
    // ============ generic-arch fallback (compile-only on GB300) ============
    for (int c = tid; c < KC; c += NTHR) {
        float s = 0.0f;
        const float* cr = cbk + c * DD;
        for (int k = 0; k < DD; ++k) {
            float v = cr[k];
            s = __fadd_rn(s, __fmul_rn(v, v));
        }
        Cs[c] = s;
    }
    __syncthreads();
    for (long long row = (long long)bid * NTHR + tid; row < n; row += (long long)gridDim.x * NTHR) {
        const float* xr = x + row * DD;
        float xv[DD];
        for (int k = 0; k < DD; ++k) xv[k] = xr[k];
        float xs = 0.0f;
        for (int k = 0; k < DD; ++k) xs = __fadd_rn(xs, __fmul_rn(xv[k], xv[k]));
        float best = 3.4e38f; int bi = 0;
        for (int c = 0; c < KC; ++c) {
            const float* cr = cbk + c * DD;
            float dot = 0.0f;
            for (int k = 0; k < DD; ++k) dot = __fmaf_rn(xv[k], cr[k], dot);
            float d = __fmaf_rn(-2.0f, dot, __fadd_rn(xs, Cs[c]));
            if (d < best) { best = d; bi = c; }
        }
        out[2 * nD + row] = (float)bi;
        const float* cr = cbk + bi * DD;
        for (int k = 0; k < DD; ++k) {
            out[(size_t)row * DD + k] = cr[k];
            out[nD + (size_t)row * DD + k] = cr[k];
        }
    }
#endif
}

extern "C" void kernel_launch(void* const* d_in, const int* in_sizes, int n_in,
                              void* d_out, int out_size) {
    const float* x = (const float*)d_in[0];
    const float* cbk = (const float*)d_in[1];
    float* out = (float*)d_out;
    const int n = in_sizes[0] / DD;

    cudaFuncSetAttribute(vq_persist, cudaFuncAttributeMaxDynamicSharedMemorySize, SMEM_TOTAL);
    vq_persist<<<NCTA, NTHR, SMEM_TOTAL>>>(x, cbk, out, n);
}